// round 1
// baseline (speedup 1.0000x reference)
#include <cuda_runtime.h>

// Problem constants (fixed by the reference):
//   x:   (1, 16, 1024, 1024) f32   -> d_in[0]
//   img: (16, 1024, 1024)    f32   -> d_in[1]
//   index_x: (L,1) i32             -> d_in[2]
//   index_y: (L,1) i32             -> d_in[3]
//   proj_x:  (L,)  i32             -> d_in[4]
//   proj_y:  (L,)  i32             -> d_in[5]
//   out: (16, 1024, 1024) f32
// out = x[0]; out[c, ix, iy] += img[c, proj_y, proj_x]  (atomic due to dup indices)

#define CHW (16 * 1024 * 1024)
#define HW  (1024 * 1024)

__global__ void copy_kernel(const float4* __restrict__ src, float4* __restrict__ dst, int n4) {
    int i = blockIdx.x * blockDim.x + threadIdx.x;
    int stride = gridDim.x * blockDim.x;
    for (; i < n4; i += stride) {
        dst[i] = src[i];
    }
}

__global__ void scatter_kernel(const float* __restrict__ img,
                               const int* __restrict__ index_x,
                               const int* __restrict__ index_y,
                               const int* __restrict__ proj_x,
                               const int* __restrict__ proj_y,
                               float* __restrict__ out,
                               int L) {
    int l = blockIdx.x * blockDim.x + threadIdx.x;
    if (l >= L) return;

    const int ix = index_x[l];
    const int iy = index_y[l];
    const int px = proj_x[l];
    const int py = proj_y[l];

    const int src = py * 1024 + px;   // gather position within a channel plane
    const int dst = ix * 1024 + iy;   // scatter position within a channel plane

    // Gather all 16 channels first (MLP=16 hides L2/DRAM latency), then fire
    // 16 no-return atomics (REDG).
    float v[16];
#pragma unroll
    for (int c = 0; c < 16; c++) {
        v[c] = __ldg(img + c * HW + src);
    }
#pragma unroll
    for (int c = 0; c < 16; c++) {
        atomicAdd(out + c * HW + dst, v[c]);
    }
}

extern "C" void kernel_launch(void* const* d_in, const int* in_sizes, int n_in,
                              void* d_out, int out_size) {
    const float* x       = (const float*)d_in[0];
    const float* img     = (const float*)d_in[1];
    const int*   index_x = (const int*)d_in[2];
    const int*   index_y = (const int*)d_in[3];
    const int*   proj_x  = (const int*)d_in[4];
    const int*   proj_y  = (const int*)d_in[5];
    float*       out     = (float*)d_out;

    const int L = in_sizes[2];

    // Phase 1: out = x[0]  (64 MB copy, vectorized)
    {
        int n4 = CHW / 4;
        int threads = 256;
        int blocks = 148 * 8;  // grid-stride, a few waves
        copy_kernel<<<blocks, threads>>>((const float4*)x, (float4*)out, n4);
    }

    // Phase 2: scatter-add (must run after copy; stream ordering guarantees it)
    {
        int threads = 256;
        int blocks = (L + threads - 1) / threads;
        scatter_kernel<<<blocks, threads>>>(img, index_x, index_y, proj_x, proj_y, out, L);
    }
}

// round 2
// speedup vs baseline: 4.5302x; 4.5302x over previous
#include <cuda_runtime.h>

// out = x[0]; out[c, ix, iy] += img[c, proj_y, proj_x]
// Strategy: transpose to position-major scratch so the 16 channels of one
// record are 64 B contiguous (2 sectors) on both gather and scatter sides.
//   accT[p][c] = x[0][c][p]        (folds the out=x copy)
//   imgT[p][c] = img[c][p]
//   scatter: accT[dst][0..16) += imgT[src][0..16)  via red.global.add.v4.f32
//   out[c][p] = accT[p][c]

#define HW (1024 * 1024)
#define NC 16

// Scratch (allowed: __device__ globals, not runtime allocation)
__device__ float g_imgT[(size_t)HW * NC];
__device__ float g_accT[(size_t)HW * NC];

__device__ __forceinline__ void red_add_v4(float* ptr, float4 v) {
    asm volatile("red.global.add.v4.f32 [%0], {%1, %2, %3, %4};"
                 :: "l"(ptr), "f"(v.x), "f"(v.y), "f"(v.z), "f"(v.w)
                 : "memory");
}

// Transpose x and img into position-major scratch.
// Reads are coalesced (consecutive threads -> consecutive p within a plane).
__global__ void transpose_fwd(const float* __restrict__ x,
                              const float* __restrict__ img) {
    int p = blockIdx.x * blockDim.x + threadIdx.x;
    if (p >= HW) return;

    float a[NC], b[NC];
#pragma unroll
    for (int c = 0; c < NC; c++) {
        a[c] = __ldg(x   + (size_t)c * HW + p);
        b[c] = __ldg(img + (size_t)c * HW + p);
    }
    float4* accT = (float4*)(g_accT + (size_t)p * NC);
    float4* imgT = (float4*)(g_imgT + (size_t)p * NC);
#pragma unroll
    for (int i = 0; i < 4; i++) {
        accT[i] = make_float4(a[4*i], a[4*i+1], a[4*i+2], a[4*i+3]);
        imgT[i] = make_float4(b[4*i], b[4*i+1], b[4*i+2], b[4*i+3]);
    }
}

__global__ void scatter_kernel(const int* __restrict__ index_x,
                               const int* __restrict__ index_y,
                               const int* __restrict__ proj_x,
                               const int* __restrict__ proj_y,
                               int L) {
    int l = blockIdx.x * blockDim.x + threadIdx.x;
    if (l >= L) return;

    const int ix = index_x[l];
    const int iy = index_y[l];
    const int px = proj_x[l];
    const int py = proj_y[l];

    const size_t src = (size_t)(py * 1024 + px) * NC;
    const size_t dst = (size_t)(ix * 1024 + iy) * NC;

    const float4* s = (const float4*)(g_imgT + src);
    float4 v0 = __ldg(s + 0);
    float4 v1 = __ldg(s + 1);
    float4 v2 = __ldg(s + 2);
    float4 v3 = __ldg(s + 3);

    float* d = g_accT + dst;
    red_add_v4(d + 0,  v0);
    red_add_v4(d + 4,  v1);
    red_add_v4(d + 8,  v2);
    red_add_v4(d + 12, v3);
}

// accT (position-major) -> out (channel-major). Writes coalesced.
__global__ void transpose_back(float* __restrict__ out) {
    int p = blockIdx.x * blockDim.x + threadIdx.x;
    if (p >= HW) return;

    const float4* accT = (const float4*)(g_accT + (size_t)p * NC);
    float4 v[4];
#pragma unroll
    for (int i = 0; i < 4; i++) v[i] = accT[i];
    const float* f = (const float*)v;
#pragma unroll
    for (int c = 0; c < NC; c++) {
        out[(size_t)c * HW + p] = f[c];
    }
}

extern "C" void kernel_launch(void* const* d_in, const int* in_sizes, int n_in,
                              void* d_out, int out_size) {
    const float* x       = (const float*)d_in[0];
    const float* img     = (const float*)d_in[1];
    const int*   index_x = (const int*)d_in[2];
    const int*   index_y = (const int*)d_in[3];
    const int*   proj_x  = (const int*)d_in[4];
    const int*   proj_y  = (const int*)d_in[5];
    float*       out     = (float*)d_out;

    const int L = in_sizes[2];

    {
        int threads = 256;
        int blocks = (HW + threads - 1) / threads;
        transpose_fwd<<<blocks, threads>>>(x, img);
    }
    {
        int threads = 256;
        int blocks = (L + threads - 1) / threads;
        scatter_kernel<<<blocks, threads>>>(index_x, index_y, proj_x, proj_y, L);
    }
    {
        int threads = 256;
        int blocks = (HW + threads - 1) / threads;
        transpose_back<<<blocks, threads>>>(out);
    }
}

// round 4
// speedup vs baseline: 4.8602x; 1.0728x over previous
#include <cuda_runtime.h>

// out = x[0]; out[c, ix, iy] += img[c, proj_y, proj_x]
// R4 = R3 with the host-side __device__-symbol-address bug fixed:
// channel-split position-major layout so each scatter pass's working set
// (imgT_h 32MB + accT_h 32MB) fits in L2 (126MB) -> no thrash.
//   imgT_h[p][j] = img[8h+j][p]   (j=0..7, 32 B per record = 1 sector)
//   accT_h[p][j] = x[0][8h+j][p]
//   pass h: accT_h[dst] += imgT_h[src]  via 2x red.global.add.v4.f32
//   finish: out[c][p] = accT_{c/8}[p][c%8]

#define HW (1024 * 1024)
#define LMAX 4000000

__device__ float g_imgT0[(size_t)HW * 8];
__device__ float g_imgT1[(size_t)HW * 8];
__device__ float g_accT0[(size_t)HW * 8];
__device__ float g_accT1[(size_t)HW * 8];
__device__ int2  g_pk[LMAX];

__device__ __forceinline__ void red_add_v4(float* ptr, float4 v) {
    asm volatile("red.global.add.v4.f32 [%0], {%1, %2, %3, %4};"
                 :: "l"(ptr), "f"(v.x), "f"(v.y), "f"(v.z), "f"(v.w)
                 : "memory");
}

// Transpose x -> accT halves, img -> imgT halves. Reads coalesced.
__global__ void prep_kernel(const float* __restrict__ x,
                            const float* __restrict__ img) {
    int p = blockIdx.x * blockDim.x + threadIdx.x;
    if (p >= HW) return;

    float a[16], b[16];
#pragma unroll
    for (int c = 0; c < 16; c++) {
        a[c] = __ldg(x   + (size_t)c * HW + p);
        b[c] = __ldg(img + (size_t)c * HW + p);
    }
    float4* a0 = (float4*)(g_accT0 + (size_t)p * 8);
    float4* a1 = (float4*)(g_accT1 + (size_t)p * 8);
    float4* b0 = (float4*)(g_imgT0 + (size_t)p * 8);
    float4* b1 = (float4*)(g_imgT1 + (size_t)p * 8);
    a0[0] = make_float4(a[0], a[1], a[2], a[3]);
    a0[1] = make_float4(a[4], a[5], a[6], a[7]);
    a1[0] = make_float4(a[8], a[9], a[10], a[11]);
    a1[1] = make_float4(a[12], a[13], a[14], a[15]);
    b0[0] = make_float4(b[0], b[1], b[2], b[3]);
    b0[1] = make_float4(b[4], b[5], b[6], b[7]);
    b1[0] = make_float4(b[8], b[9], b[10], b[11]);
    b1[1] = make_float4(b[12], b[13], b[14], b[15]);
}

// Pack (src, dst) per record: 16 B of index reads -> 8 B packed.
__global__ void pack_kernel(const int* __restrict__ index_x,
                            const int* __restrict__ index_y,
                            const int* __restrict__ proj_x,
                            const int* __restrict__ proj_y,
                            int L) {
    int l = blockIdx.x * blockDim.x + threadIdx.x;
    if (l >= L) return;
    int src = __ldg(proj_y  + l) * 1024 + __ldg(proj_x  + l);
    int dst = __ldg(index_x + l) * 1024 + __ldg(index_y + l);
    g_pk[l] = make_int2(src, dst);
}

// One channel-half scatter pass: 64 MB working set, L2 resident.
// Half selected device-side (passing __device__ symbol addresses from host is UB).
template <int HALF>
__global__ void scatter_half(int L) {
    const float* __restrict__ imgTh = (HALF == 0) ? g_imgT0 : g_imgT1;
    float* __restrict__ accTh       = (HALF == 0) ? g_accT0 : g_accT1;

    int l = blockIdx.x * blockDim.x + threadIdx.x;
    if (l >= L) return;
    int2 k = __ldg(&g_pk[l]);
    const float4* s = (const float4*)(imgTh + (size_t)k.x * 8);
    float4 v0 = __ldg(s + 0);
    float4 v1 = __ldg(s + 1);
    float* d = accTh + (size_t)k.y * 8;
    red_add_v4(d + 0, v0);
    red_add_v4(d + 4, v1);
}

// accT halves (position-major) -> out (channel-major). Writes coalesced.
__global__ void finish_kernel(float* __restrict__ out) {
    int p = blockIdx.x * blockDim.x + threadIdx.x;
    if (p >= HW) return;

    const float4* a0 = (const float4*)(g_accT0 + (size_t)p * 8);
    const float4* a1 = (const float4*)(g_accT1 + (size_t)p * 8);
    float4 v[4];
    v[0] = a0[0]; v[1] = a0[1]; v[2] = a1[0]; v[3] = a1[1];
    const float* f = (const float*)v;
#pragma unroll
    for (int c = 0; c < 16; c++) {
        out[(size_t)c * HW + p] = f[c];
    }
}

extern "C" void kernel_launch(void* const* d_in, const int* in_sizes, int n_in,
                              void* d_out, int out_size) {
    const float* x       = (const float*)d_in[0];
    const float* img     = (const float*)d_in[1];
    const int*   index_x = (const int*)d_in[2];
    const int*   index_y = (const int*)d_in[3];
    const int*   proj_x  = (const int*)d_in[4];
    const int*   proj_y  = (const int*)d_in[5];
    float*       out     = (float*)d_out;

    const int L = in_sizes[2];

    const int T = 256;
    prep_kernel<<<(HW + T - 1) / T, T>>>(x, img);
    pack_kernel<<<(L + T - 1) / T, T>>>(index_x, index_y, proj_x, proj_y, L);
    scatter_half<0><<<(L + T - 1) / T, T>>>(L);
    scatter_half<1><<<(L + T - 1) / T, T>>>(L);
    finish_kernel<<<(HW + T - 1) / T, T>>>(out);
}